// round 2
// baseline (speedup 1.0000x reference)
#include <cuda_runtime.h>

#define NWIN 512
#define NTOK 512
#define DIMC 192
#define SCALE_F 0.17677669529663687f
#define MROWS (NWIN*NTOK)

__device__ float g_q  [(size_t)MROWS * DIMC];
__device__ float g_kvp[(size_t)MROWS * 48];
__device__ float g_ao [(size_t)MROWS * DIMC];
__device__ float g_bias[6 * NTOK * 64];

typedef unsigned long long u64;

__device__ __forceinline__ u64 pk2(float x, float y){ u64 r; asm("mov.b64 %0,{%1,%2};":"=l"(r):"f"(x),"f"(y)); return r; }
__device__ __forceinline__ void upk2(u64 v, float& x, float& y){ asm("mov.b64 {%0,%1},%2;":"=f"(x),"=f"(y):"l"(v)); }
__device__ __forceinline__ void ffma2(u64& d, u64 a, u64 b){ asm("fma.rn.f32x2 %0,%1,%2,%0;":"+l"(d):"l"(a),"l"(b)); }

// ---------------- K0: bias[h][n][p] = table[rpi[n,p], h] ----------------
__global__ __launch_bounds__(256) void bias_gather_kernel(
    const float* __restrict__ table, const int* __restrict__ rpi)
{
  int idx = blockIdx.x*256 + threadIdx.x;       // 6*512*64 = 196608
  int hh = idx >> 15;
  int np = idx & 32767;
  g_bias[idx] = table[rpi[np]*6 + hh];
}

// ------------- K1/K2/K4: C = (A @ W + bias) * scale, K=192 -------------
// SRC: 0=param A, 1=g_ao.  DST: 0=g_q, 1=g_kvp, 2=param C.
template<int NC, int SRC, int DST>
__global__ __launch_bounds__(256) void gemm_k192(
    const float* __restrict__ Ain, const float* __restrict__ W,
    const float* __restrict__ bias, float* __restrict__ Cout, float scale)
{
  constexpr int TX = NC/12;      // 16 or 4
  constexpr int TY = 256/TX;     // 16 or 64
  constexpr int RY = 64/TY;      // 4  or 1
  __shared__ alignas(16) float As[64*36];
  __shared__ alignas(16) float Ws[32*NC];
  const float* A = (SRC==0) ? Ain : g_ao;
  float* C = (DST==0) ? g_q : (DST==1) ? g_kvp : Cout;

  const int tid = threadIdx.x;
  const int row0 = blockIdx.x * 64;
  const int tx = tid % TX, ty = tid / TX;
  const int rr = tid >> 2, q4 = tid & 3;

  u64 acc[RY][6];
#pragma unroll
  for (int i=0;i<RY;i++)
#pragma unroll
    for (int j=0;j<6;j++) acc[i][j] = 0ull;

  for (int kc = 0; kc < 6; kc++) {
    // A tile: 64 rows x 32 k
    const float* ga = A + (size_t)(row0+rr)*192 + kc*32 + q4*8;
    *(float4*)&As[rr*36 + q4*8]     = *(const float4*)ga;
    *(float4*)&As[rr*36 + q4*8 + 4] = *(const float4*)(ga+4);
    // W chunk: rows kc*32..+32 contiguous
    const float4* gw = (const float4*)(W + (size_t)kc*32*NC);
    float4* sw = (float4*)Ws;
    for (int i = tid; i < 32*NC/4; i += 256) sw[i] = gw[i];
    __syncthreads();

#pragma unroll 8
    for (int k = 0; k < 32; k++) {
      const ulonglong2* bp = (const ulonglong2*)(Ws + k*NC + tx*12);
      ulonglong2 b01 = bp[0], b23 = bp[1], b45 = bp[2];
#pragma unroll
      for (int i=0;i<RY;i++) {
        u64 av = pk2(As[(ty*RY+i)*36 + k], As[(ty*RY+i)*36 + k]);
        ffma2(acc[i][0], av, b01.x); ffma2(acc[i][1], av, b01.y);
        ffma2(acc[i][2], av, b23.x); ffma2(acc[i][3], av, b23.y);
        ffma2(acc[i][4], av, b45.x); ffma2(acc[i][5], av, b45.y);
      }
    }
    __syncthreads();
  }
  // epilogue
#pragma unroll
  for (int i=0;i<RY;i++) {
    int row = row0 + ty*RY + i;
#pragma unroll
    for (int j=0;j<6;j++) {
      float x, y; upk2(acc[i][j], x, y);
      int col = tx*12 + j*2;
      float2 o;
      o.x = (x + bias[col])   * scale;
      o.y = (y + bias[col+1]) * scale;
      *(float2*)&C[(size_t)row*NC + col] = o;
    }
  }
}

// ---------------- K3: attention per (qtile, head, window) ----------------
__global__ __launch_bounds__(128) void attn_kernel()
{
  __shared__ alignas(16) float ks[32*64];   // [d][p]  (K transposed)
  __shared__ alignas(16) float vs[64*32];   // [p][d]
  const int qt = blockIdx.x, h = blockIdx.y, b = blockIdx.z;
  const int tid = threadIdx.x;
  const float* kvb = g_kvp + (size_t)b*512*48;

  // gather K and V with the 2x2x2 spatial fold
  for (int e = tid; e < 2048; e += 128) {
    int p = e >> 5, d = e & 31;
    int f = h*32 + d;                       // K: kv_sel=0
    int abc = f/48, ch = f - abc*48;
    int n = (((p>>4)*2 + (abc>>2)) << 6) | ((((p>>2)&3)*2 + ((abc>>1)&1)) << 3)
          | ((p&3)*2 + (abc&1));
    ks[d*64 + p] = kvb[n*48 + ch];
    int f2 = f + 192;                       // V: kv_sel=1
    int abc2 = f2/48, ch2 = f2 - abc2*48;
    int n2 = (((p>>4)*2 + (abc2>>2)) << 6) | ((((p>>2)&3)*2 + ((abc2>>1)&1)) << 3)
           | ((p&3)*2 + (abc2&1));
    vs[p*32 + d] = kvb[n2*48 + ch2];
  }
  __syncthreads();

  const int n = qt*128 + tid;
  const size_t qoff = ((size_t)(b*512 + n))*192 + h*32;
  float q[32];
#pragma unroll
  for (int i=0;i<8;i++) *(float4*)&q[i*4] = *(const float4*)&g_q[qoff + i*4];

  // init scores with bias
  u64 s2[32];
  const float4* b4 = (const float4*)(g_bias + ((h*512 + n) << 6));
#pragma unroll
  for (int i=0;i<16;i++){ float4 t = b4[i]; s2[2*i]=pk2(t.x,t.y); s2[2*i+1]=pk2(t.z,t.w); }

  // GEMM1: S = Q K^T (+bias), q pre-scaled in K1
#pragma unroll 4
  for (int d=0; d<32; d++) {
    u64 qd = pk2(q[d], q[d]);
    const ulonglong2* kp = (const ulonglong2*)(ks + d*64);
#pragma unroll
    for (int j=0;j<16;j++){ ulonglong2 kk = kp[j]; ffma2(s2[2*j], qd, kk.x); ffma2(s2[2*j+1], qd, kk.y); }
  }

  // softmax (row-local; 1/sum folded into output)
  float s[64];
#pragma unroll
  for (int i=0;i<32;i++) upk2(s2[i], s[2*i], s[2*i+1]);
  float m = s[0];
#pragma unroll
  for (int i=1;i<64;i++) m = fmaxf(m, s[i]);
  float sum = 0.f;
#pragma unroll
  for (int i=0;i<64;i++){ s[i] = __expf(s[i]-m); sum += s[i]; }
  float inv = __frcp_rn(sum);

  // GEMM2: O = P V
  u64 o2[16];
#pragma unroll
  for (int j=0;j<16;j++) o2[j] = 0ull;
#pragma unroll 4
  for (int p=0;p<64;p++) {
    u64 sp = pk2(s[p], s[p]);
    const ulonglong2* vp = (const ulonglong2*)(vs + p*32);
#pragma unroll
    for (int j=0;j<8;j++){ ulonglong2 vv = vp[j]; ffma2(o2[2*j], sp, vv.x); ffma2(o2[2*j+1], sp, vv.y); }
  }

  float* op = g_ao + qoff;
#pragma unroll
  for (int j=0;j<16;j++) {
    float x, y; upk2(o2[j], x, y);
    float2 o; o.x = x*inv; o.y = y*inv;
    *(float2*)&op[2*j] = o;
  }
}

// ------------------------------ launcher ------------------------------
extern "C" void kernel_launch(void* const* d_in, const int* in_sizes, int n_in,
                              void* d_out, int out_size)
{
  const float* x     = (const float*)d_in[0];
  const float* wq    = (const float*)d_in[1];
  const float* bq    = (const float*)d_in[2];
  const float* wkv   = (const float*)d_in[3];
  const float* bkv   = (const float*)d_in[4];
  const float* table = (const float*)d_in[5];
  const float* wproj = (const float*)d_in[6];
  const float* bproj = (const float*)d_in[7];
  const int*   rpi   = (const int*)  d_in[8];
  float* out = (float*)d_out;

  bias_gather_kernel<<<768, 256>>>(table, rpi);
  gemm_k192<192,0,0><<<MROWS/64, 256>>>(x, wq,    bq,    nullptr, SCALE_F); // q
  gemm_k192< 48,0,1><<<MROWS/64, 256>>>(x, wkv,   bkv,   nullptr, 1.0f);    // kv
  attn_kernel<<<dim3(4,6,NWIN), 128>>>();
  gemm_k192<192,1,2><<<MROWS/64, 256>>>(nullptr, wproj, bproj, out, 1.0f);  // proj
}

// round 5
// speedup vs baseline: 1.2177x; 1.2177x over previous
#include <cuda_runtime.h>

#define NWIN 512
#define NTOK 512
#define DIMC 192
#define SCALE_F 0.17677669529663687f
#define MROWS (NWIN*NTOK)

__device__ float g_q  [(size_t)MROWS * DIMC];
__device__ float g_kvp[(size_t)MROWS * 48];
__device__ float g_ao [(size_t)MROWS * DIMC];
__device__ float g_bias[6 * NTOK * 64];

typedef unsigned long long u64;

__device__ __forceinline__ u64 pk2(float x, float y){ u64 r; asm("mov.b64 %0,{%1,%2};":"=l"(r):"f"(x),"f"(y)); return r; }
__device__ __forceinline__ void upk2(u64 v, float& x, float& y){ asm("mov.b64 {%0,%1},%2;":"=f"(x),"=f"(y):"l"(v)); }
__device__ __forceinline__ void ffma2(u64& d, u64 a, u64 b){ asm("fma.rn.f32x2 %0,%1,%2,%0;":"+l"(d):"l"(a),"l"(b)); }

// ---------------- K0: bias[h][n][p] = table[rpi[n,p], h] ----------------
__global__ __launch_bounds__(256) void bias_gather_kernel(
    const float* __restrict__ table, const int* __restrict__ rpi)
{
  int idx = blockIdx.x*256 + threadIdx.x;
  int hh = idx >> 15;
  int np = idx & 32767;
  g_bias[idx] = table[rpi[np]*6 + hh];
}

// ------------- K1/K2/K4: C = (A @ W + bias) * scale, K=192 -------------
template<int NC, int SRC, int DST>
__global__ __launch_bounds__(256) void gemm_k192(
    const float* __restrict__ Ain, const float* __restrict__ W,
    const float* __restrict__ bias, float* __restrict__ Cout, float scale)
{
  constexpr int TX = NC/12;
  constexpr int TY = 256/TX;
  constexpr int RY = 64/TY;
  __shared__ alignas(16) float As[64*36];
  __shared__ alignas(16) float Ws[32*NC];
  const float* A = (SRC==0) ? Ain : g_ao;
  float* C = (DST==0) ? g_q : (DST==1) ? g_kvp : Cout;

  const int tid = threadIdx.x;
  const int row0 = blockIdx.x * 64;
  const int tx = tid % TX, ty = tid / TX;
  const int rr = tid >> 2, q4 = tid & 3;

  u64 acc[RY][6];
#pragma unroll
  for (int i=0;i<RY;i++)
#pragma unroll
    for (int j=0;j<6;j++) acc[i][j] = 0ull;

  for (int kc = 0; kc < 6; kc++) {
    const float* ga = A + (size_t)(row0+rr)*192 + kc*32 + q4*8;
    *(float4*)&As[rr*36 + q4*8]     = *(const float4*)ga;
    *(float4*)&As[rr*36 + q4*8 + 4] = *(const float4*)(ga+4);
    const float4* gw = (const float4*)(W + (size_t)kc*32*NC);
    float4* sw = (float4*)Ws;
    for (int i = tid; i < 32*NC/4; i += 256) sw[i] = gw[i];
    __syncthreads();

#pragma unroll
    for (int k4 = 0; k4 < 8; k4++) {
      float a4[RY][4];
#pragma unroll
      for (int i=0;i<RY;i++)
        *(float4*)a4[i] = *(const float4*)&As[(ty*RY+i)*36 + k4*4];
#pragma unroll
      for (int kk = 0; kk < 4; kk++) {
        const int k = k4*4 + kk;
        const ulonglong2* bp = (const ulonglong2*)(Ws + k*NC + tx*12);
        ulonglong2 b01 = bp[0], b23 = bp[1], b45 = bp[2];
#pragma unroll
        for (int i=0;i<RY;i++) {
          u64 av = pk2(a4[i][kk], a4[i][kk]);
          ffma2(acc[i][0], av, b01.x); ffma2(acc[i][1], av, b01.y);
          ffma2(acc[i][2], av, b23.x); ffma2(acc[i][3], av, b23.y);
          ffma2(acc[i][4], av, b45.x); ffma2(acc[i][5], av, b45.y);
        }
      }
    }
    __syncthreads();
  }
#pragma unroll
  for (int i=0;i<RY;i++) {
    int row = row0 + ty*RY + i;
#pragma unroll
    for (int j=0;j<6;j++) {
      float x, y; upk2(acc[i][j], x, y);
      int col = tx*12 + j*2;
      float2 o;
      o.x = (x + bias[col])   * scale;
      o.y = (y + bias[col+1]) * scale;
      *(float2*)&C[(size_t)row*NC + col] = o;
    }
  }
}

// ---------------- K3: attention, register-tiled GEMMs ----------------
// arena: [0..4096)    qs  [d][m]  32x128 (swizzled cols)  -- dead after G1
//        [4096..6144) ks  [d][p]  32x64                   -- dead after G1
//        [0..8192)    Ps  [p][m]  64x128 (swizzled cols)  -- overlays qs/ks
//        [8192..10240) vs [p][d]  64x32
__global__ __launch_bounds__(128) void attn_kernel()
{
  __shared__ alignas(16) float arena[10240];
  float* qs = arena;
  float* ks = arena + 4096;
  float* Ps = arena;
  float* vs = arena + 8192;

  const int qt = blockIdx.x, h = blockIdx.y, b = blockIdx.z;
  const int tid = threadIdx.x;
  const float* kvb = g_kvp + (size_t)b*512*48;

  // gather K (2x2x2 fold): lanes vary p -> conflict-free STS
  {
    int p = tid & 63, dbase = tid >> 6;
#pragma unroll
    for (int k = 0; k < 16; k++) {
      int d = dbase + 2*k;
      int f = h*32 + d;
      int abc = f/48, ch = f - abc*48;
      int n = (((p>>4)*2 + (abc>>2)) << 6) | ((((p>>2)&3)*2 + ((abc>>1)&1)) << 3)
            | ((p&3)*2 + (abc&1));
      ks[d*64 + p] = kvb[n*48 + ch];
    }
  }
  // gather V: lanes vary d -> conflict-free STS
  {
    int d = tid & 31, pbase = tid >> 5;
#pragma unroll
    for (int k = 0; k < 16; k++) {
      int p = pbase + 4*k;
      int f2 = h*32 + d + 192;
      int abc2 = f2/48, ch2 = f2 - abc2*48;
      int n2 = (((p>>4)*2 + (abc2>>2)) << 6) | ((((p>>2)&3)*2 + ((abc2>>1)&1)) << 3)
             | ((p&3)*2 + (abc2&1));
      vs[p*32 + d] = kvb[n2*48 + ch2];
    }
  }
  // load Q transposed into qs[d][m^sw(d)], sw(d)=(((d>>1)&7)<<2)
  {
#pragma unroll
    for (int k = 0; k < 8; k++) {
      int f = tid + k*128;
      int m = f >> 3, c4 = f & 7;
      const float4 v = *(const float4*)&g_q[((size_t)(b*512 + qt*128 + m))*192 + h*32 + c4*4];
      float vv[4] = {v.x, v.y, v.z, v.w};
#pragma unroll
      for (int j = 0; j < 4; j++) {
        int d = c4*4 + j;
        int sw = ((d>>1)&7) << 2;
        qs[d*128 + (m ^ sw)] = vv[j];
      }
    }
  }
  __syncthreads();

  // ---- GEMM1: S = Q K^T + bias.  thread (ty 0..15, tx 0..7): 8m x 8p ----
  const int ty = tid >> 3, tx = tid & 7;
  u64 s2[8][4];
#pragma unroll
  for (int i = 0; i < 8; i++) {
    const float4* bp = (const float4*)&g_bias[((h*512 + qt*128 + ty*8 + i) << 6) + tx*8];
    float4 t0 = bp[0], t1 = bp[1];
    s2[i][0] = pk2(t0.x, t0.y); s2[i][1] = pk2(t0.z, t0.w);
    s2[i][2] = pk2(t1.x, t1.y); s2[i][3] = pk2(t1.z, t1.w);
  }

#pragma unroll 4
  for (int d = 0; d < 32; d++) {
    int sw = ((d>>1)&7) << 2;
    float4 a0 = *(const float4*)&qs[d*128 + ((ty*8    ) ^ sw)];
    float4 a1 = *(const float4*)&qs[d*128 + ((ty*8 + 4) ^ sw)];
    const ulonglong2* kp = (const ulonglong2*)(ks + d*64 + tx*8);
    ulonglong2 k0 = kp[0], k1 = kp[1];
    float af[8] = {a0.x,a0.y,a0.z,a0.w,a1.x,a1.y,a1.z,a1.w};
#pragma unroll
    for (int i = 0; i < 8; i++) {
      u64 av = pk2(af[i], af[i]);
      ffma2(s2[i][0], av, k0.x); ffma2(s2[i][1], av, k0.y);
      ffma2(s2[i][2], av, k1.x); ffma2(s2[i][3], av, k1.y);
    }
  }

  // ---- softmax over rows (8 lanes per row, bfly width 8) ----
  float s[8][8];
#pragma unroll
  for (int i = 0; i < 8; i++) {
    upk2(s2[i][0], s[i][0], s[i][1]); upk2(s2[i][1], s[i][2], s[i][3]);
    upk2(s2[i][2], s[i][4], s[i][5]); upk2(s2[i][3], s[i][6], s[i][7]);
  }
#pragma unroll
  for (int i = 0; i < 8; i++) {
    float mx = s[i][0];
#pragma unroll
    for (int j = 1; j < 8; j++) mx = fmaxf(mx, s[i][j]);
    mx = fmaxf(mx, __shfl_xor_sync(0xffffffffu, mx, 1, 8));
    mx = fmaxf(mx, __shfl_xor_sync(0xffffffffu, mx, 2, 8));
    mx = fmaxf(mx, __shfl_xor_sync(0xffffffffu, mx, 4, 8));
    float sm = 0.f;
#pragma unroll
    for (int j = 0; j < 8; j++) { s[i][j] = __expf(s[i][j] - mx); sm += s[i][j]; }
    sm += __shfl_xor_sync(0xffffffffu, sm, 1, 8);
    sm += __shfl_xor_sync(0xffffffffu, sm, 2, 8);
    sm += __shfl_xor_sync(0xffffffffu, sm, 4, 8);
    float inv = __frcp_rn(sm);
#pragma unroll
    for (int j = 0; j < 8; j++) s[i][j] *= inv;
  }

  __syncthreads();   // all reads of qs/ks complete before Ps overlays them

  // store P transposed: Ps[p][m ^ ((p>>3)<<2)]
  {
    int sw2 = tx << 2;   // p>>3 == tx for p = tx*8+j
#pragma unroll
    for (int j = 0; j < 8; j++) {
      int p = tx*8 + j;
      float4 v0 = make_float4(s[0][j], s[1][j], s[2][j], s[3][j]);
      float4 v1 = make_float4(s[4][j], s[5][j], s[6][j], s[7][j]);
      *(float4*)&Ps[p*128 + ((ty*8    ) ^ sw2)] = v0;
      *(float4*)&Ps[p*128 + ((ty*8 + 4) ^ sw2)] = v1;
    }
  }
  __syncthreads();

  // ---- GEMM2: O = P V.  thread (ty2 0..31, tx2 0..3): 4m x 8d ----
  const int ty2 = tid >> 2, tx2 = tid & 3;
  u64 o2[4][4];
#pragma unroll
  for (int i = 0; i < 4; i++)
#pragma unroll
    for (int j = 0; j < 4; j++) o2[i][j] = 0ull;

#pragma unroll 4
  for (int p = 0; p < 64; p++) {
    int sw2 = ((p>>3)&7) << 2;
    float4 a = *(const float4*)&Ps[p*128 + ((ty2*4) ^ sw2)];
    const ulonglong2* vp = (const ulonglong2*)(vs + p*32 + tx2*8);
    ulonglong2 v0 = vp[0], v1 = vp[1];
    float af[4] = {a.x, a.y, a.z, a.w};
#pragma unroll
    for (int i = 0; i < 4; i++) {
      u64 av = pk2(af[i], af[i]);
      ffma2(o2[i][0], av, v0.x); ffma2(o2[i][1], av, v0.y);
      ffma2(o2[i][2], av, v1.x); ffma2(o2[i][3], av, v1.y);
    }
  }

#pragma unroll
  for (int i = 0; i < 4; i++) {
    float o[8];
    upk2(o2[i][0], o[0], o[1]); upk2(o2[i][1], o[2], o[3]);
    upk2(o2[i][2], o[4], o[5]); upk2(o2[i][3], o[6], o[7]);
    float* op = g_ao + ((size_t)(b*512 + qt*128 + ty2*4 + i))*192 + h*32 + tx2*8;
    *(float4*)&op[0] = make_float4(o[0], o[1], o[2], o[3]);
    *(float4*)&op[4] = make_float4(o[4], o[5], o[6], o[7]);
  }
}

// ------------------------------ launcher ------------------------------
extern "C" void kernel_launch(void* const* d_in, const int* in_sizes, int n_in,
                              void* d_out, int out_size)
{
  const float* x     = (const float*)d_in[0];
  const float* wq    = (const float*)d_in[1];
  const float* bq    = (const float*)d_in[2];
  const float* wkv   = (const float*)d_in[3];
  const float* bkv   = (const float*)d_in[4];
  const float* table = (const float*)d_in[5];
  const float* wproj = (const float*)d_in[6];
  const float* bproj = (const float*)d_in[7];
  const int*   rpi   = (const int*)  d_in[8];
  float* out = (float*)d_out;

  bias_gather_kernel<<<768, 256>>>(table, rpi);
  gemm_k192<192,0,0><<<MROWS/64, 256>>>(x, wq,    bq,    nullptr, SCALE_F);
  gemm_k192< 48,0,1><<<MROWS/64, 256>>>(x, wkv,   bkv,   nullptr, 1.0f);
  attn_kernel<<<dim3(4,6,NWIN), 128>>>();
  gemm_k192<192,1,2><<<MROWS/64, 256>>>(nullptr, wproj, bproj, out, 1.0f);
}

// round 7
// speedup vs baseline: 1.3375x; 1.0984x over previous
#include <cuda_runtime.h>

#define NWIN 512
#define NTOK 512
#define DIMC 192
#define SCALE_F 0.17677669529663687f
#define MROWS (NWIN*NTOK)

__device__ float g_q  [(size_t)MROWS * DIMC];
__device__ float g_kvp[(size_t)MROWS * 48];
__device__ float g_ao [(size_t)MROWS * DIMC];
__device__ float g_bias[6 * NTOK * 64];

typedef unsigned long long u64;

__device__ __forceinline__ u64 pk2(float x, float y){ u64 r; asm("mov.b64 %0,{%1,%2};":"=l"(r):"f"(x),"f"(y)); return r; }
__device__ __forceinline__ void upk2(u64 v, float& x, float& y){ asm("mov.b64 {%0,%1},%2;":"=f"(x),"=f"(y):"l"(v)); }
__device__ __forceinline__ void ffma2(u64& d, u64 a, u64 b){ asm("fma.rn.f32x2 %0,%1,%2,%0;":"+l"(d):"l"(a),"l"(b)); }

// ---------------- K0: bias[h][n][p] = table[rpi[n,p], h] ----------------
__global__ __launch_bounds__(256) void bias_gather_kernel(
    const float* __restrict__ table, const int* __restrict__ rpi)
{
  int idx = blockIdx.x*256 + threadIdx.x;
  int hh = idx >> 15;
  int np = idx & 32767;
  g_bias[idx] = table[rpi[np]*6 + hh];
}

// ------------- K1/K2/K4: C = (A @ W + bias) * scale, K=192 -------------
// Register-staged double buffer: next kc's A/W global loads issue right
// after this kc's STS+sync, hidden behind the 32-k FFMA block.
template<int NC, int SRC, int DST>
__global__ __launch_bounds__(256) void gemm_k192(
    const float* __restrict__ Ain, const float* __restrict__ W,
    const float* __restrict__ bias, float* __restrict__ Cout, float scale)
{
  constexpr int TX = NC/12;
  constexpr int TY = 256/TX;
  constexpr int RY = 64/TY;
  constexpr int NW4 = 32*NC/4;              // float4s per W chunk
  constexpr int NL  = (NW4 + 255)/256;      // per-thread W frag count
  __shared__ alignas(16) float As[64*36];
  __shared__ alignas(16) float Ws[32*NC];
  const float* A = (SRC==0) ? Ain : g_ao;
  float* C = (DST==0) ? g_q : (DST==1) ? g_kvp : Cout;

  const int tid = threadIdx.x;
  const int row0 = blockIdx.x * 64;
  const int tx = tid % TX, ty = tid / TX;
  const int rr = tid >> 2, q4 = tid & 3;

  u64 acc[RY][6];
#pragma unroll
  for (int i=0;i<RY;i++)
#pragma unroll
    for (int j=0;j<6;j++) acc[i][j] = 0ull;

  const float* ga = A + (size_t)(row0+rr)*192 + q4*8;
  const float4* gw = (const float4*)W;

  // prologue: stage kc=0
  float4 a0 = *(const float4*)ga;
  float4 a1 = *(const float4*)(ga+4);
  float4 wb[NL];
#pragma unroll
  for (int i=0;i<NL;i++) if (i*256 + tid < NW4) wb[i] = gw[i*256 + tid];

  for (int kc = 0; kc < 6; kc++) {
    *(float4*)&As[rr*36 + q4*8]     = a0;
    *(float4*)&As[rr*36 + q4*8 + 4] = a1;
    float4* sw = (float4*)Ws;
#pragma unroll
    for (int i=0;i<NL;i++) if (i*256 + tid < NW4) sw[i*256 + tid] = wb[i];
    __syncthreads();

    if (kc < 5) {  // prefetch next chunk while computing
      a0 = *(const float4*)(ga + (kc+1)*32);
      a1 = *(const float4*)(ga + (kc+1)*32 + 4);
#pragma unroll
      for (int i=0;i<NL;i++) if (i*256 + tid < NW4)
        wb[i] = gw[(size_t)(kc+1)*NW4 + i*256 + tid];
    }

#pragma unroll
    for (int k4 = 0; k4 < 8; k4++) {
      float a4[RY][4];
#pragma unroll
      for (int i=0;i<RY;i++)
        *(float4*)a4[i] = *(const float4*)&As[(ty*RY+i)*36 + k4*4];
#pragma unroll
      for (int kk = 0; kk < 4; kk++) {
        const int k = k4*4 + kk;
        const ulonglong2* bp = (const ulonglong2*)(Ws + k*NC + tx*12);
        ulonglong2 b01 = bp[0], b23 = bp[1], b45 = bp[2];
#pragma unroll
        for (int i=0;i<RY;i++) {
          u64 av = pk2(a4[i][kk], a4[i][kk]);
          ffma2(acc[i][0], av, b01.x); ffma2(acc[i][1], av, b01.y);
          ffma2(acc[i][2], av, b23.x); ffma2(acc[i][3], av, b23.y);
          ffma2(acc[i][4], av, b45.x); ffma2(acc[i][5], av, b45.y);
        }
      }
    }
    __syncthreads();
  }
#pragma unroll
  for (int i=0;i<RY;i++) {
    int row = row0 + ty*RY + i;
#pragma unroll
    for (int j=0;j<6;j++) {
      float x, y; upk2(acc[i][j], x, y);
      int col = tx*12 + j*2;
      float2 o;
      o.x = (x + bias[col])   * scale;
      o.y = (y + bias[col+1]) * scale;
      *(float2*)&C[(size_t)row*NC + col] = o;
    }
  }
}

// ---------------- K3: attention, one CTA per (head, window) ----------------
// arena floats: [0..8192)    Ps  [p][m] 64x128 (swizzled)  / qs [d][m] 32x128 overlays
//               [8192..10240)  ks [d][p] 32x64   (persists across qt loop)
//               [10240..12288) vs [p][d] 64x32   (persists across qt loop)
__global__ __launch_bounds__(128) void attn_kernel()
{
  __shared__ alignas(16) float arena[12288];   // 48 KB exactly
  float* qs = arena;
  float* Ps = arena;
  float* ks = arena + 8192;
  float* vs = arena + 10240;

  const int h = blockIdx.x, b = blockIdx.y;
  const int tid = threadIdx.x;
  const float* kvb = g_kvp + (size_t)b*512*48;

  // gather K (2x2x2 fold): lanes vary p -> conflict-free STS
  {
    int p = tid & 63, dbase = tid >> 6;
#pragma unroll
    for (int k = 0; k < 16; k++) {
      int d = dbase + 2*k;
      int f = h*32 + d;
      int abc = f/48, ch = f - abc*48;
      int n = (((p>>4)*2 + (abc>>2)) << 6) | ((((p>>2)&3)*2 + ((abc>>1)&1)) << 3)
            | ((p&3)*2 + (abc&1));
      ks[d*64 + p] = kvb[n*48 + ch];
    }
  }
  // gather V: lanes vary d -> conflict-free STS
  {
    int d = tid & 31, pbase = tid >> 5;
#pragma unroll
    for (int k = 0; k < 16; k++) {
      int p = pbase + 4*k;
      int f2 = h*32 + d + 192;
      int abc2 = f2/48, ch2 = f2 - abc2*48;
      int n2 = (((p>>4)*2 + (abc2>>2)) << 6) | ((((p>>2)&3)*2 + ((abc2>>1)&1)) << 3)
             | ((p&3)*2 + (abc2&1));
      vs[p*32 + d] = kvb[n2*48 + ch2];
    }
  }

  const int ty = tid >> 3, tx = tid & 7;      // GEMM1 map: 8m x 8p
  const int ty2 = tid >> 2, tx2 = tid & 3;    // GEMM2 map: 4m x 8d

  for (int qt = 0; qt < 4; qt++) {
    // load Q transposed into qs[d][m^sw(d)], sw(d)=(((d>>1)&7)<<2)
#pragma unroll
    for (int k = 0; k < 8; k++) {
      int f = tid + k*128;
      int m = f >> 3, c4 = f & 7;
      const float4 v = *(const float4*)&g_q[((size_t)(b*512 + qt*128 + m))*192 + h*32 + c4*4];
      float vv[4] = {v.x, v.y, v.z, v.w};
#pragma unroll
      for (int j = 0; j < 4; j++) {
        int d = c4*4 + j;
        int sw = ((d>>1)&7) << 2;
        qs[d*128 + (m ^ sw)] = vv[j];
      }
    }
    __syncthreads();   // qs (and on qt=0, ks/vs) ready

    // ---- GEMM1: S = Q K^T + bias ----
    u64 s2[8][4];
#pragma unroll
    for (int i = 0; i < 8; i++) {
      const float4* bp = (const float4*)&g_bias[((h*512 + qt*128 + ty*8 + i) << 6) + tx*8];
      float4 t0 = bp[0], t1 = bp[1];
      s2[i][0] = pk2(t0.x, t0.y); s2[i][1] = pk2(t0.z, t0.w);
      s2[i][2] = pk2(t1.x, t1.y); s2[i][3] = pk2(t1.z, t1.w);
    }

#pragma unroll 4
    for (int d = 0; d < 32; d++) {
      int sw = ((d>>1)&7) << 2;
      float4 a0 = *(const float4*)&qs[d*128 + ((ty*8    ) ^ sw)];
      float4 a1 = *(const float4*)&qs[d*128 + ((ty*8 + 4) ^ sw)];
      const ulonglong2* kp = (const ulonglong2*)(ks + d*64 + tx*8);
      ulonglong2 k0 = kp[0], k1 = kp[1];
      float af[8] = {a0.x,a0.y,a0.z,a0.w,a1.x,a1.y,a1.z,a1.w};
#pragma unroll
      for (int i = 0; i < 8; i++) {
        u64 av = pk2(af[i], af[i]);
        ffma2(s2[i][0], av, k0.x); ffma2(s2[i][1], av, k0.y);
        ffma2(s2[i][2], av, k1.x); ffma2(s2[i][3], av, k1.y);
      }
    }

    // ---- softmax over rows (8 lanes per row, bfly width 8) ----
    float s[8][8];
#pragma unroll
    for (int i = 0; i < 8; i++) {
      upk2(s2[i][0], s[i][0], s[i][1]); upk2(s2[i][1], s[i][2], s[i][3]);
      upk2(s2[i][2], s[i][4], s[i][5]); upk2(s2[i][3], s[i][6], s[i][7]);
    }
#pragma unroll
    for (int i = 0; i < 8; i++) {
      float mx = s[i][0];
#pragma unroll
      for (int j = 1; j < 8; j++) mx = fmaxf(mx, s[i][j]);
      mx = fmaxf(mx, __shfl_xor_sync(0xffffffffu, mx, 1, 8));
      mx = fmaxf(mx, __shfl_xor_sync(0xffffffffu, mx, 2, 8));
      mx = fmaxf(mx, __shfl_xor_sync(0xffffffffu, mx, 4, 8));
      float sm = 0.f;
#pragma unroll
      for (int j = 0; j < 8; j++) { s[i][j] = __expf(s[i][j] - mx); sm += s[i][j]; }
      sm += __shfl_xor_sync(0xffffffffu, sm, 1, 8);
      sm += __shfl_xor_sync(0xffffffffu, sm, 2, 8);
      sm += __shfl_xor_sync(0xffffffffu, sm, 4, 8);
      float inv = __frcp_rn(sm);
#pragma unroll
      for (int j = 0; j < 8; j++) s[i][j] *= inv;
    }

    __syncthreads();   // all qs reads done before Ps overlays

    // store P transposed: Ps[p][m ^ ((p>>3)<<2)]
    {
      int sw2 = tx << 2;
#pragma unroll
      for (int j = 0; j < 8; j++) {
        int p = tx*8 + j;
        float4 v0 = make_float4(s[0][j], s[1][j], s[2][j], s[3][j]);
        float4 v1 = make_float4(s[4][j], s[5][j], s[6][j], s[7][j]);
        *(float4*)&Ps[p*128 + ((ty*8    ) ^ sw2)] = v0;
        *(float4*)&Ps[p*128 + ((ty*8 + 4) ^ sw2)] = v1;
      }
    }
    __syncthreads();

    // ---- GEMM2: O = P V ----
    u64 o2[4][4];
#pragma unroll
    for (int i = 0; i < 4; i++)
#pragma unroll
      for (int j = 0; j < 4; j++) o2[i][j] = 0ull;

#pragma unroll 4
    for (int p = 0; p < 64; p++) {
      int sw2 = ((p>>3)&7) << 2;
      float4 a = *(const float4*)&Ps[p*128 + ((ty2*4) ^ sw2)];
      const ulonglong2* vp = (const ulonglong2*)(vs + p*32 + tx2*8);
      ulonglong2 v0 = vp[0], v1 = vp[1];
      float af[4] = {a.x, a.y, a.z, a.w};
#pragma unroll
      for (int i = 0; i < 4; i++) {
        u64 av = pk2(af[i], af[i]);
        ffma2(o2[i][0], av, v0.x); ffma2(o2[i][1], av, v0.y);
        ffma2(o2[i][2], av, v1.x); ffma2(o2[i][3], av, v1.y);
      }
    }

#pragma unroll
    for (int i = 0; i < 4; i++) {
      float o[8];
      upk2(o2[i][0], o[0], o[1]); upk2(o2[i][1], o[2], o[3]);
      upk2(o2[i][2], o[4], o[5]); upk2(o2[i][3], o[6], o[7]);
      float* op = g_ao + ((size_t)(b*512 + qt*128 + ty2*4 + i))*192 + h*32 + tx2*8;
      *(float4*)&op[0] = make_float4(o[0], o[1], o[2], o[3]);
      *(float4*)&op[4] = make_float4(o[4], o[5], o[6], o[7]);
    }
    __syncthreads();   // Ps reads done before next qt's qs fill
  }
}

// ------------------------------ launcher ------------------------------
extern "C" void kernel_launch(void* const* d_in, const int* in_sizes, int n_in,
                              void* d_out, int out_size)
{
  const float* x     = (const float*)d_in[0];
  const float* wq    = (const float*)d_in[1];
  const float* bq    = (const float*)d_in[2];
  const float* wkv   = (const float*)d_in[3];
  const float* bkv   = (const float*)d_in[4];
  const float* table = (const float*)d_in[5];
  const float* wproj = (const float*)d_in[6];
  const float* bproj = (const float*)d_in[7];
  const int*   rpi   = (const int*)  d_in[8];
  float* out = (float*)d_out;

  bias_gather_kernel<<<768, 256>>>(table, rpi);
  gemm_k192<192,0,0><<<MROWS/64, 256>>>(x, wq,    bq,    nullptr, SCALE_F);
  gemm_k192< 48,0,1><<<MROWS/64, 256>>>(x, wkv,   bkv,   nullptr, 1.0f);
  attn_kernel<<<dim3(6, NWIN), 128>>>();
  gemm_k192<192,1,2><<<MROWS/64, 256>>>(nullptr, wproj, bproj, out, 1.0f);
}

// round 9
// speedup vs baseline: 1.7185x; 1.2849x over previous
#include <cuda_runtime.h>
#include <cuda_bf16.h>

#define NWIN 512
#define NTOK 512
#define SCALE_F 0.17677669529663687f
#define MROWS (NWIN*NTOK)

typedef unsigned int u32;
typedef unsigned long long u64;

__device__ float g_q  [(size_t)MROWS * 192];
__device__ float g_kvp[(size_t)MROWS * 48];
__device__ float g_ao [(size_t)MROWS * 192];
__device__ float g_bias[6 * NTOK * 64];
// W transposed+split: [which][n*192+k], which: 0=wq, 1=wproj
__device__ __nv_bfloat16 g_wt_hi[2][192*192];
__device__ __nv_bfloat16 g_wt_lo[2][192*192];

__device__ __forceinline__ u64 pk2(float x, float y){ u64 r; asm("mov.b64 %0,{%1,%2};":"=l"(r):"f"(x),"f"(y)); return r; }
__device__ __forceinline__ void upk2(u64 v, float& x, float& y){ asm("mov.b64 {%0,%1},%2;":"=f"(x),"=f"(y):"l"(v)); }
__device__ __forceinline__ void ffma2(u64& d, u64 a, u64 b){ asm("fma.rn.f32x2 %0,%1,%2,%0;":"+l"(d):"l"(a),"l"(b)); }

__device__ __forceinline__ void ldsm4(u32& r0, u32& r1, u32& r2, u32& r3, u32 addr){
  asm volatile("ldmatrix.sync.aligned.m8n8.x4.shared.b16 {%0,%1,%2,%3}, [%4];"
               : "=r"(r0),"=r"(r1),"=r"(r2),"=r"(r3) : "r"(addr));
}
__device__ __forceinline__ void mma16816(float* c, const u32* a, u32 b0, u32 b1){
  asm volatile("mma.sync.aligned.m16n8k16.row.col.f32.bf16.bf16.f32 "
               "{%0,%1,%2,%3}, {%4,%5,%6,%7}, {%8,%9}, {%0,%1,%2,%3};"
               : "+f"(c[0]),"+f"(c[1]),"+f"(c[2]),"+f"(c[3])
               : "r"(a[0]),"r"(a[1]),"r"(a[2]),"r"(a[3]), "r"(b0),"r"(b1));
}

// ---------------- K0: bias[h][n][p] = table[rpi[n,p], h] ----------------
__global__ __launch_bounds__(256) void bias_gather_kernel(
    const float* __restrict__ table, const int* __restrict__ rpi)
{
  int idx = blockIdx.x*256 + threadIdx.x;
  int hh = idx >> 15;
  int np = idx & 32767;
  g_bias[idx] = table[rpi[np]*6 + hh];
}

// ---------------- W transpose + bf16 hi/lo split ----------------
__global__ __launch_bounds__(512) void wsplit_kernel(
    const float* __restrict__ wq, const float* __restrict__ wproj)
{
  int idx = blockIdx.x*512 + threadIdx.x;       // 2*36864 = 73728
  int which = idx / 36864;
  int r = idx - which*36864;
  int n = r / 192, k = r - n*192;
  float v = (which ? wproj : wq)[k*192 + n];
  __nv_bfloat16 h = __float2bfloat16_rn(v);
  __nv_bfloat16 l = __float2bfloat16_rn(v - __bfloat162float(h));
  g_wt_hi[which][n*192 + k] = h;
  g_wt_lo[which][n*192 + k] = l;
}

// ------- K1/K4: C = (A @ W + bias) * scale via bf16 mma, 3-pass split -------
// CTA: 128 rows x 192 cols, K in 12 chunks of 16. 512 thr = 16 warps (4m x 4n),
// warp tile 32m x 48n. smem pitch 24 bf16 (48B, ldmatrix conflict-free).
// WSEL: weight set (0=wq, 1=wproj). SRC: 0=param A, 1=g_ao. DST: 0=g_q, 1=param C.
template<int WSEL, int SRC, int DST>
__global__ __launch_bounds__(512) void gemm_mma(
    const float* __restrict__ Ain, const float* __restrict__ bias,
    float* __restrict__ Cout, float scale)
{
  __shared__ __nv_bfloat16 sA[2][128*24];   // [hi/lo][row*24 + k]
  __shared__ __nv_bfloat16 sB[2][192*24];   // [hi/lo][n*24 + k]
  const float* A = (SRC==0) ? Ain : g_ao;
  float* C = (DST==0) ? g_q : Cout;
  const __nv_bfloat16* bth = g_wt_hi[WSEL];
  const __nv_bfloat16* btl = g_wt_lo[WSEL];

  const int tid = threadIdx.x;
  const int row0 = blockIdx.x * 128;
  const int warp = tid >> 5, lane = tid & 31;
  const int mrow = (warp & 3) * 32;
  const int ncol = (warp >> 2) * 48;

  float acc[2][6][4];
#pragma unroll
  for (int mt=0;mt<2;mt++){
#pragma unroll
    for (int j=0;j<6;j++){
#pragma unroll
      for (int q=0;q<4;q++){ acc[mt][j][q] = 0.f; }
    }
  }

  // A fill map: arow = tid/4 (0..127), aseg = tid%4 (4 floats each)
  const int arow = tid >> 2, aseg = tid & 3;
  const float* gA = A + (size_t)(row0 + arow)*192 + aseg*4;
  // B fill map: 3 units of 4 bf16 per thread: f = tid + i*512 in [0,1536)
  int bn[3], bpart[3], bver[3];
  const __nv_bfloat16* gB[3];
#pragma unroll
  for (int i=0;i<3;i++){
    int f = tid + i*512;
    bver[i] = f / 768;
    int r = f - bver[i]*768;
    bn[i] = r >> 2; bpart[i] = r & 3;
    gB[i] = (bver[i] ? btl : bth) + bn[i]*192 + bpart[i]*4;
  }

  // prologue: stage chunk 0
  float4 apf = *(const float4*)gA;
  float2 bpf[3];
#pragma unroll
  for (int i=0;i<3;i++){ bpf[i] = *(const float2*)gB[i]; }

  // ldmatrix shared addresses
  u32 saA0 = (u32)__cvta_generic_to_shared(&sA[0][0]);
  u32 saA1 = (u32)__cvta_generic_to_shared(&sA[1][0]);
  u32 saB0 = (u32)__cvta_generic_to_shared(&sB[0][0]);
  u32 saB1 = (u32)__cvta_generic_to_shared(&sB[1][0]);
  const u32 lrow = (u32)(lane & 15);
  const u32 lcol = (u32)((lane >> 4) * 16);   // byte offset for k8-15 half
  const u32 adA0 = saA0 + (mrow + lrow)*48 + lcol;
  const u32 adA1 = saA1 + (mrow + lrow)*48 + lcol;
  const u32 adB0 = saB0 + (ncol + lrow)*48 + lcol;
  const u32 adB1 = saB1 + (ncol + lrow)*48 + lcol;

  const int astore = arow*24 + aseg*4;   // bf16 index

  for (int kc = 0; kc < 12; kc++) {
    // ---- STS staged chunk (convert A fp32 -> bf16 hi/lo) ----
    {
      __nv_bfloat16 ha = __float2bfloat16_rn(apf.x);
      __nv_bfloat16 hb = __float2bfloat16_rn(apf.y);
      __nv_bfloat16 hc = __float2bfloat16_rn(apf.z);
      __nv_bfloat16 hd = __float2bfloat16_rn(apf.w);
      __nv_bfloat16 la = __float2bfloat16_rn(apf.x - __bfloat162float(ha));
      __nv_bfloat16 lb = __float2bfloat16_rn(apf.y - __bfloat162float(hb));
      __nv_bfloat16 lc = __float2bfloat16_rn(apf.z - __bfloat162float(hc));
      __nv_bfloat16 ld = __float2bfloat16_rn(apf.w - __bfloat162float(hd));
      *(__nv_bfloat162*)&sA[0][astore]     = __halves2bfloat162(ha, hb);
      *(__nv_bfloat162*)&sA[0][astore + 2] = __halves2bfloat162(hc, hd);
      *(__nv_bfloat162*)&sA[1][astore]     = __halves2bfloat162(la, lb);
      *(__nv_bfloat162*)&sA[1][astore + 2] = __halves2bfloat162(lc, ld);
#pragma unroll
      for (int i=0;i<3;i++){
        *(float2*)&sB[bver[i]][bn[i]*24 + bpart[i]*4] = bpf[i];
      }
    }
    __syncthreads();

    if (kc < 11) {   // prefetch next chunk during compute
      apf = *(const float4*)(gA + (kc+1)*16);
#pragma unroll
      for (int i=0;i<3;i++){ bpf[i] = *(const float2*)(gB[i] + (kc+1)*16); }
    }

    // ---- ldmatrix + mma ----
    u32 ah[2][4], al[2][4];
#pragma unroll
    for (int mt=0;mt<2;mt++){
      ldsm4(ah[mt][0], ah[mt][1], ah[mt][2], ah[mt][3], adA0 + mt*16*48);
      ldsm4(al[mt][0], al[mt][1], al[mt][2], al[mt][3], adA1 + mt*16*48);
    }
#pragma unroll
    for (int ng=0;ng<3;ng++){
      u32 bh0,bh1,bh2,bh3, bl0,bl1,bl2,bl3;
      ldsm4(bh0,bh1,bh2,bh3, adB0 + ng*16*48);
      ldsm4(bl0,bl1,bl2,bl3, adB1 + ng*16*48);
#pragma unroll
      for (int mt=0;mt<2;mt++){
        mma16816(acc[mt][ng*2],   ah[mt], bh0, bh2);
        mma16816(acc[mt][ng*2],   ah[mt], bl0, bl2);
        mma16816(acc[mt][ng*2],   al[mt], bh0, bh2);
        mma16816(acc[mt][ng*2+1], ah[mt], bh1, bh3);
        mma16816(acc[mt][ng*2+1], ah[mt], bl1, bl3);
        mma16816(acc[mt][ng*2+1], al[mt], bh1, bh3);
      }
    }
    __syncthreads();
  }

  // ---- epilogue: c-frag lane l: rows l/4, l/4+8; cols (l&3)*2, +1 ----
#pragma unroll
  for (int mt=0;mt<2;mt++){
#pragma unroll
    for (int j=0;j<6;j++){
      int col = ncol + j*8 + (lane & 3)*2;
      float2 bv = *(const float2*)&bias[col];
      int rg = row0 + mrow + mt*16 + (lane >> 2);
      float2 o0, o1;
      o0.x = (acc[mt][j][0] + bv.x) * scale;
      o0.y = (acc[mt][j][1] + bv.y) * scale;
      o1.x = (acc[mt][j][2] + bv.x) * scale;
      o1.y = (acc[mt][j][3] + bv.y) * scale;
      *(float2*)&C[(size_t)rg*192 + col]     = o0;
      *(float2*)&C[(size_t)(rg+8)*192 + col] = o1;
    }
  }
}

// ------------- K2: kv = x @ wkv + bkv (fp32 SIMT, NC=48) -------------
__global__ __launch_bounds__(256) void gemm_kv(
    const float* __restrict__ A, const float* __restrict__ W,
    const float* __restrict__ bias)
{
  const int NC = 48;
  const int NW4 = 32*NC/4;    // 384
  const int NL  = 2;          // ceil(384/256)
  __shared__ alignas(16) float As[64*36];
  __shared__ alignas(16) float Ws[32*NC];
  float* C = g_kvp;

  const int tid = threadIdx.x;
  const int row0 = blockIdx.x * 64;
  const int tx = tid % 4, ty = tid / 4;
  const int rr = tid >> 2, q4 = tid & 3;

  u64 acc[6];
#pragma unroll
  for (int j=0;j<6;j++){ acc[j] = 0ull; }

  const float* ga = A + (size_t)(row0+rr)*192 + q4*8;
  const float4* gw = (const float4*)W;

  float4 a0 = *(const float4*)ga;
  float4 a1 = *(const float4*)(ga+4);
  float4 wb[NL];
#pragma unroll
  for (int i=0;i<NL;i++){ if (i*256 + tid < NW4) wb[i] = gw[i*256 + tid]; }

  for (int kc = 0; kc < 6; kc++) {
    *(float4*)&As[rr*36 + q4*8]     = a0;
    *(float4*)&As[rr*36 + q4*8 + 4] = a1;
    float4* swp = (float4*)Ws;
#pragma unroll
    for (int i=0;i<NL;i++){ if (i*256 + tid < NW4) swp[i*256 + tid] = wb[i]; }
    __syncthreads();

    if (kc < 5) {
      a0 = *(const float4*)(ga + (kc+1)*32);
      a1 = *(const float4*)(ga + (kc+1)*32 + 4);
#pragma unroll
      for (int i=0;i<NL;i++){
        if (i*256 + tid < NW4) wb[i] = gw[(size_t)(kc+1)*NW4 + i*256 + tid];
      }
    }

#pragma unroll
    for (int k4 = 0; k4 < 8; k4++) {
      float a4[4];
      *(float4*)a4 = *(const float4*)&As[ty*36 + k4*4];
#pragma unroll
      for (int kk = 0; kk < 4; kk++) {
        const int k = k4*4 + kk;
        const ulonglong2* bp = (const ulonglong2*)(Ws + k*NC + tx*12);
        ulonglong2 b01 = bp[0], b23 = bp[1], b45 = bp[2];
        u64 av = pk2(a4[kk], a4[kk]);
        ffma2(acc[0], av, b01.x); ffma2(acc[1], av, b01.y);
        ffma2(acc[2], av, b23.x); ffma2(acc[3], av, b23.y);
        ffma2(acc[4], av, b45.x); ffma2(acc[5], av, b45.y);
      }
    }
    __syncthreads();
  }
  int row = row0 + ty;
#pragma unroll
  for (int j=0;j<6;j++) {
    float x, y; upk2(acc[j], x, y);
    int col = tx*12 + j*2;
    float2 o;
    o.x = x + bias[col];
    o.y = y + bias[col+1];
    *(float2*)&C[(size_t)row*NC + col] = o;
  }
}

// ---------------- K3: attention, one CTA per (head, window) ----------------
__global__ __launch_bounds__(128) void attn_kernel()
{
  __shared__ alignas(16) float arena[12288];
  float* qs = arena;
  float* Ps = arena;
  float* ks = arena + 8192;
  float* vs = arena + 10240;

  const int h = blockIdx.x, b = blockIdx.y;
  const int tid = threadIdx.x;
  const float* kvb = g_kvp + (size_t)b*512*48;

  {
    int p = tid & 63, dbase = tid >> 6;
#pragma unroll
    for (int k = 0; k < 16; k++) {
      int d = dbase + 2*k;
      int f = h*32 + d;
      int abc = f/48, ch = f - abc*48;
      int n = (((p>>4)*2 + (abc>>2)) << 6) | ((((p>>2)&3)*2 + ((abc>>1)&1)) << 3)
            | ((p&3)*2 + (abc&1));
      ks[d*64 + p] = kvb[n*48 + ch];
    }
  }
  {
    int d = tid & 31, pbase = tid >> 5;
#pragma unroll
    for (int k = 0; k < 16; k++) {
      int p = pbase + 4*k;
      int f2 = h*32 + d + 192;
      int abc2 = f2/48, ch2 = f2 - abc2*48;
      int n2 = (((p>>4)*2 + (abc2>>2)) << 6) | ((((p>>2)&3)*2 + ((abc2>>1)&1)) << 3)
             | ((p&3)*2 + (abc2&1));
      vs[p*32 + d] = kvb[n2*48 + ch2];
    }
  }

  const int ty = tid >> 3, tx = tid & 7;
  const int ty2 = tid >> 2, tx2 = tid & 3;

  for (int qt = 0; qt < 4; qt++) {
#pragma unroll
    for (int k = 0; k < 8; k++) {
      int f = tid + k*128;
      int m = f >> 3, c4 = f & 7;
      const float4 v = *(const float4*)&g_q[((size_t)(b*512 + qt*128 + m))*192 + h*32 + c4*4];
      float vv[4] = {v.x, v.y, v.z, v.w};
#pragma unroll
      for (int j = 0; j < 4; j++) {
        int d = c4*4 + j;
        int sw = ((d>>1)&7) << 2;
        qs[d*128 + (m ^ sw)] = vv[j];
      }
    }
    __syncthreads();

    u64 s2[8][4];
#pragma unroll
    for (int i = 0; i < 8; i++) {
      const float4* bp = (const float4*)&g_bias[((h*512 + qt*128 + ty*8 + i) << 6) + tx*8];
      float4 t0 = bp[0], t1 = bp[1];
      s2[i][0] = pk2(t0.x, t0.y); s2[i][1] = pk2(t0.z, t0.w);
      s2[i][2] = pk2(t1.x, t1.y); s2[i][3] = pk2(t1.z, t1.w);
    }

#pragma unroll 4
    for (int d = 0; d < 32; d++) {
      int sw = ((d>>1)&7) << 2;
      float4 a0 = *(const float4*)&qs[d*128 + ((ty*8    ) ^ sw)];
      float4 a1 = *(const float4*)&qs[d*128 + ((ty*8 + 4) ^ sw)];
      const ulonglong2* kp = (const ulonglong2*)(ks + d*64 + tx*8);
      ulonglong2 k0 = kp[0], k1 = kp[1];
      float af[8] = {a0.x,a0.y,a0.z,a0.w,a1.x,a1.y,a1.z,a1.w};
#pragma unroll
      for (int i = 0; i < 8; i++) {
        u64 av = pk2(af[i], af[i]);
        ffma2(s2[i][0], av, k0.x); ffma2(s2[i][1], av, k0.y);
        ffma2(s2[i][2], av, k1.x); ffma2(s2[i][3], av, k1.y);
      }
    }

    float s[8][8];
#pragma unroll
    for (int i = 0; i < 8; i++) {
      upk2(s2[i][0], s[i][0], s[i][1]); upk2(s2[i][1], s[i][2], s[i][3]);
      upk2(s2[i][2], s[i][4], s[i][5]); upk2(s2[i][3], s[i][6], s[i][7]);
    }
#pragma unroll
    for (int i = 0; i < 8; i++) {
      float mx = s[i][0];
#pragma unroll
      for (int j = 1; j < 8; j++) mx = fmaxf(mx, s[i][j]);
      mx = fmaxf(mx, __shfl_xor_sync(0xffffffffu, mx, 1, 8));
      mx = fmaxf(mx, __shfl_xor_sync(0xffffffffu, mx, 2, 8));
      mx = fmaxf(mx, __shfl_xor_sync(0xffffffffu, mx, 4, 8));
      float sm = 0.f;
#pragma unroll
      for (int j = 0; j < 8; j++) { s[i][j] = __expf(s[i][j] - mx); sm += s[i][j]; }
      sm += __shfl_xor_sync(0xffffffffu, sm, 1, 8);
      sm += __shfl_xor_sync(0xffffffffu, sm, 2, 8);
      sm += __shfl_xor_sync(0xffffffffu, sm, 4, 8);
      float inv = __frcp_rn(sm);
#pragma unroll
      for (int j = 0; j < 8; j++) s[i][j] *= inv;
    }

    __syncthreads();

    {
      int sw2 = tx << 2;
#pragma unroll
      for (int j = 0; j < 8; j++) {
        int p = tx*8 + j;
        float4 v0 = make_float4(s[0][j], s[1][j], s[2][j], s[3][j]);
        float4 v1 = make_float4(s[4][j], s[5][j], s[6][j], s[7][j]);
        *(float4*)&Ps[p*128 + ((ty*8    ) ^ sw2)] = v0;
        *(float4*)&Ps[p*128 + ((ty*8 + 4) ^ sw2)] = v1;
      }
    }
    __syncthreads();

    u64 o2[4][4];
#pragma unroll
    for (int i = 0; i < 4; i++){
#pragma unroll
      for (int j = 0; j < 4; j++){ o2[i][j] = 0ull; }
    }

#pragma unroll 4
    for (int p = 0; p < 64; p++) {
      int sw2 = ((p>>3)&7) << 2;
      float4 a = *(const float4*)&Ps[p*128 + ((ty2*4) ^ sw2)];
      const ulonglong2* vp = (const ulonglong2*)(vs + p*32 + tx2*8);
      ulonglong2 v0 = vp[0], v1 = vp[1];
      float af[4] = {a.x, a.y, a.z, a.w};
#pragma unroll
      for (int i = 0; i < 4; i++) {
        u64 av = pk2(af[i], af[i]);
        ffma2(o2[i][0], av, v0.x); ffma2(o2[i][1], av, v0.y);
        ffma2(o2[i][2], av, v1.x); ffma2(o2[i][3], av, v1.y);
      }
    }

#pragma unroll
    for (int i = 0; i < 4; i++) {
      float o[8];
      upk2(o2[i][0], o[0], o[1]); upk2(o2[i][1], o[2], o[3]);
      upk2(o2[i][2], o[4], o[5]); upk2(o2[i][3], o[6], o[7]);
      float* op = g_ao + ((size_t)(b*512 + qt*128 + ty2*4 + i))*192 + h*32 + tx2*8;
      *(float4*)&op[0] = make_float4(o[0], o[1], o[2], o[3]);
      *(float4*)&op[4] = make_float4(o[4], o[5], o[6], o[7]);
    }
    __syncthreads();
  }
}

// ------------------------------ launcher ------------------------------
extern "C" void kernel_launch(void* const* d_in, const int* in_sizes, int n_in,
                              void* d_out, int out_size)
{
  const float* x     = (const float*)d_in[0];
  const float* wq    = (const float*)d_in[1];
  const float* bq    = (const float*)d_in[2];
  const float* wkv   = (const float*)d_in[3];
  const float* bkv   = (const float*)d_in[4];
  const float* table = (const float*)d_in[5];
  const float* wproj = (const float*)d_in[6];
  const float* bproj = (const float*)d_in[7];
  const int*   rpi   = (const int*)  d_in[8];
  float* out = (float*)d_out;

  wsplit_kernel<<<144, 512>>>(wq, wproj);
  bias_gather_kernel<<<768, 256>>>(table, rpi);
  gemm_mma<0,0,0><<<MROWS/128, 512>>>(x, bq, nullptr, SCALE_F);      // q
  gemm_kv<<<MROWS/64, 256>>>(x, wkv, bkv);                           // kv
  attn_kernel<<<dim3(6, NWIN), 128>>>();
  gemm_mma<1,1,1><<<MROWS/128, 512>>>(nullptr, bproj, out, 1.0f);    // proj
}